// round 1
// baseline (speedup 1.0000x reference)
#include <cuda_runtime.h>
#include <math.h>

#define Bb 128
#define Ss 256
#define Ii 512
#define Oo 512
#define Hh 1024
#define IO 1024      // I + O
#define G3 3072      // 3*H
#define RWS (Ss*Bb)  // 32768 rows

#define TM 64
#define TN 64
#define KT 16
#define SSTR 68      // padded smem row stride (floats)

// ---------------- scratch (static __device__, allocation-free) ----------------
__device__ float g_yT[16777216];    // [s*B+b][I]   permuted y
__device__ int   g_idx[RWS];        // one-hot target index per row
__device__ float g_gi[100663296];   // [s*B+b][3H]  input-side gate preacts
__device__ float g_gh4[4*Bb*G3];    // 4 K-split partials of h @ Whh^T
__device__ float g_hs[33685504];    // [(s+1)][B][H], slot 0 = hx
__device__ float g_hsB[33554432];   // [b*S+s][H]   hs in output layout for logits GEMM

// ---------------- packed-f32x2 helpers ----------------
__device__ __forceinline__ unsigned long long pack2(float x){
    unsigned long long r;
    asm("mov.b64 %0, {%1, %1};" : "=l"(r) : "f"(x));
    return r;
}
__device__ __forceinline__ float2 unpk(unsigned long long v){
    float2 r;
    asm("mov.b64 {%0, %1}, %2;" : "=f"(r.x), "=f"(r.y) : "l"(v));
    return r;
}
#define FF(d,a,b) asm("fma.rn.f32x2 %0, %1, %2, %0;" : "+l"(d) : "l"(a), "l"(b))

// ---------------- shared GEMM core: C[64x64] tile of A[M,K] @ W[N,K]^T ----------------
// 256 threads, 4x4 micro-tile per thread, f32x2 packed FMA (2 fp32 FMA / instr).
__device__ __forceinline__ void gemm_core(
    const float* __restrict__ A, int lda,
    const float* __restrict__ W, int ldw,
    int rowBase, int colBase, int k0, int nk,
    unsigned long long acc[4][2])
{
    __shared__ __align__(16) float shA[KT*SSTR];
    __shared__ __align__(16) float shB[KT*SSTR];
    const int tid = threadIdx.x;
    const int tx = tid & 15, ty = tid >> 4;
    const int lk = tid & 15, lm = tid >> 4;

    for (int kc = 0; kc < nk; ++kc) {
        const int kb = k0 + kc*KT + lk;
        #pragma unroll
        for (int i = 0; i < 4; ++i) {
            shA[lk*SSTR + lm + i*16] = A[(size_t)(rowBase + lm + i*16)*lda + kb];
            shB[lk*SSTR + lm + i*16] = W[(size_t)(colBase + lm + i*16)*ldw + kb];
        }
        __syncthreads();
        #pragma unroll
        for (int kk = 0; kk < KT; ++kk) {
            float4 av = *reinterpret_cast<const float4*>(shA + kk*SSTR + (ty<<2));
            ulonglong2 bv = *reinterpret_cast<const ulonglong2*>(shB + kk*SSTR + (tx<<2));
            unsigned long long a0=pack2(av.x), a1=pack2(av.y), a2=pack2(av.z), a3=pack2(av.w);
            FF(acc[0][0],a0,bv.x); FF(acc[0][1],a0,bv.y);
            FF(acc[1][0],a1,bv.x); FF(acc[1][1],a1,bv.y);
            FF(acc[2][0],a2,bv.x); FF(acc[2][1],a2,bv.y);
            FF(acc[3][0],a3,bv.x); FF(acc[3][1],a3,bv.y);
        }
        __syncthreads();
    }
}

// ---------------- prep kernels ----------------
// One warp per row r = s*B+b: find index of the one-hot teacher-forcing target.
__global__ void k_idx(const float* __restrict__ gt, const float* __restrict__ gotoken){
    int w = (blockIdx.x*blockDim.x + threadIdx.x) >> 5;
    int lane = threadIdx.x & 31;
    if (w >= RWS) return;
    int s = w / Bb, b = w % Bb;
    const float* src = (s == 0) ? gotoken : gt + ((size_t)b*Ss + (s-1))*Oo;
    int found = Oo - 1;
    for (int o = lane; o < Oo; o += 32)
        if (src[o] > 0.5f) found = o;
    #pragma unroll
    for (int off = 16; off; off >>= 1)
        found = min(found, __shfl_xor_sync(0xffffffffu, found, off));
    if (lane == 0) g_idx[w] = found;
}

// Permute y[b][s][i] -> yT[s*B+b][i]
__global__ void k_yT(const float* __restrict__ y){
    size_t t = (size_t)blockIdx.x*blockDim.x + threadIdx.x;
    if (t >= (size_t)RWS*Ii) return;
    int i = (int)(t % Ii); int r = (int)(t / Ii);
    int s = r / Bb, b = r % Bb;
    g_yT[t] = y[((size_t)b*Ss + s)*Ii + i];
}

__global__ void k_h0(const float* __restrict__ hx){
    int t = blockIdx.x*blockDim.x + threadIdx.x;
    if (t < Bb*Hh) g_hs[t] = hx[t];
}

// ---------------- gi GEMM: gi[r][g] = yT[r]·Wih[g,:I] + bih[g] + Wih[g, I+idx[r]] ----------------
__global__ void k_gi(const float* __restrict__ Wih, const float* __restrict__ bih){
    unsigned long long acc[4][2] = {};
    int rowBase = blockIdx.y*TM, colBase = blockIdx.x*TN;
    gemm_core(g_yT, Ii, Wih, IO, rowBase, colBase, 0, Ii/KT, acc);
    int tx = threadIdx.x & 15, ty = threadIdx.x >> 4;
    #pragma unroll
    for (int i = 0; i < 4; ++i){
        int row = rowBase + (ty<<2) + i;
        int idx = g_idx[row];
        #pragma unroll
        for (int j = 0; j < 2; ++j){
            float2 v = unpk(acc[i][j]);
            int n = colBase + (tx<<2) + (j<<1);
            g_gi[(size_t)row*G3 + n]     = v.x + bih[n]   + Wih[(size_t)n*IO + Ii + idx];
            g_gi[(size_t)row*G3 + n + 1] = v.y + bih[n+1] + Wih[(size_t)(n+1)*IO + Ii + idx];
        }
    }
}

// ---------------- per-step GEMM: gh partial = h_prev @ Whh^T, K split 4 ways ----------------
__global__ void k_gh(const float* __restrict__ Whh, int s){
    unsigned long long acc[4][2] = {};
    int rowBase = blockIdx.y*TM, colBase = blockIdx.x*TN;
    int kz = blockIdx.z;
    const float* hprev = g_hs + (size_t)s*Bb*Hh;
    gemm_core(hprev, Hh, Whh, Hh, rowBase, colBase, kz*(Hh/4), (Hh/4)/KT, acc);
    int tx = threadIdx.x & 15, ty = threadIdx.x >> 4;
    float* dst = g_gh4 + (size_t)kz*Bb*G3;
    #pragma unroll
    for (int i = 0; i < 4; ++i){
        int row = rowBase + (ty<<2) + i;
        #pragma unroll
        for (int j = 0; j < 2; ++j){
            float2 v = unpk(acc[i][j]);
            int n = colBase + (tx<<2) + (j<<1);
            dst[(size_t)row*G3 + n]   = v.x;
            dst[(size_t)row*G3 + n+1] = v.y;
        }
    }
}

// ---------------- per-step gates (sums the 4 K-split partials, fixed order) ----------------
__global__ void k_gates(const float* __restrict__ bhh, float* __restrict__ pre_out, int s){
    int t = blockIdx.x*blockDim.x + threadIdx.x;
    if (t >= Bb*Hh) return;
    int b = t >> 10, j = t & 1023;
    size_t gio = ((size_t)s*Bb + b)*G3 + j;
    float i_r = g_gi[gio], i_z = g_gi[gio + Hh], i_n = g_gi[gio + 2*Hh];
    size_t gho = (size_t)b*G3 + j;
    float h_r = bhh[j], h_z = bhh[Hh + j], h_n = bhh[2*Hh + j];
    #pragma unroll
    for (int kz = 0; kz < 4; ++kz){
        size_t o = (size_t)kz*Bb*G3 + gho;
        h_r += g_gh4[o]; h_z += g_gh4[o + Hh]; h_n += g_gh4[o + 2*Hh];
    }
    float rg = 1.f/(1.f + expf(-(i_r + h_r)));
    float zg = 1.f/(1.f + expf(-(i_z + h_z)));
    float pre = i_n + rg*h_n;
    float ng = tanhf(pre);
    float hp = g_hs[((size_t)s*Bb + b)*Hh + j];
    float hy = ng + zg*(hp - ng);
    g_hs [((size_t)(s+1)*Bb + b)*Hh + j] = hy;
    g_hsB[((size_t)b*Ss + s)*Hh + j]     = hy;
    pre_out[((size_t)b*Ss + s)*Hh + j]   = pre;
}

// ---------------- logits GEMM: logits[b*S+s][o] = hsB·lin_w[o]^T + lin_b[o] ----------------
__global__ void k_logits(const float* __restrict__ lw, const float* __restrict__ lb,
                         float* __restrict__ outp){
    unsigned long long acc[4][2] = {};
    int rowBase = blockIdx.y*TM, colBase = blockIdx.x*TN;
    gemm_core(g_hsB, Hh, lw, Hh, rowBase, colBase, 0, Hh/KT, acc);
    int tx = threadIdx.x & 15, ty = threadIdx.x >> 4;
    #pragma unroll
    for (int i = 0; i < 4; ++i){
        int row = rowBase + (ty<<2) + i;
        #pragma unroll
        for (int j = 0; j < 2; ++j){
            float2 v = unpk(acc[i][j]);
            int n = colBase + (tx<<2) + (j<<1);
            outp[(size_t)row*Oo + n]   = v.x + lb[n];
            outp[(size_t)row*Oo + n+1] = v.y + lb[n+1];
        }
    }
}

// ---------------- softmax + argmax(one-hot), in place over logits ----------------
__global__ void k_softmax(float* __restrict__ probs, float* __restrict__ samp){
    __shared__ float sv[128];
    __shared__ int   si[128];
    int row = blockIdx.x;
    int t = threadIdx.x;
    float* lg = probs + (size_t)row*Oo;
    float v[4];
    #pragma unroll
    for (int i = 0; i < 4; ++i) v[i] = lg[t + i*128];
    float lmax = v[0]; int lidx = t;
    #pragma unroll
    for (int i = 1; i < 4; ++i)
        if (v[i] > lmax){ lmax = v[i]; lidx = t + i*128; }
    sv[t] = lmax; si[t] = lidx; __syncthreads();
    for (int off = 64; off; off >>= 1){
        if (t < off){
            float v2 = sv[t+off]; int i2 = si[t+off];
            if (v2 > sv[t] || (v2 == sv[t] && i2 < si[t])){ sv[t] = v2; si[t] = i2; }
        }
        __syncthreads();
    }
    float rmax = sv[0]; int ridx = si[0];
    __syncthreads();
    float e[4]; float ls = 0.f;
    #pragma unroll
    for (int i = 0; i < 4; ++i){ e[i] = expf(v[i] - rmax); ls += e[i]; }
    sv[t] = ls; __syncthreads();
    for (int off = 64; off; off >>= 1){
        if (t < off) sv[t] += sv[t+off];
        __syncthreads();
    }
    float inv = 1.f/sv[0];
    float* sp = samp + (size_t)row*Oo;
    #pragma unroll
    for (int i = 0; i < 4; ++i){
        int p = t + i*128;
        lg[p] = e[i]*inv;
        sp[p] = (p == ridx) ? 1.f : 0.f;
    }
}

__global__ void k_hxout(float* __restrict__ out){
    int t = blockIdx.x*blockDim.x + threadIdx.x;
    if (t < Bb*Hh) out[t] = g_hs[(size_t)Ss*Bb*Hh + t];
}

// ---------------- launch ----------------
extern "C" void kernel_launch(void* const* d_in, const int* in_sizes, int n_in,
                              void* d_out, int out_size){
    const float* y    = (const float*)d_in[0];
    const float* gt   = (const float*)d_in[1];
    const float* hx   = (const float*)d_in[2];
    const float* Wih  = (const float*)d_in[3];
    const float* bih  = (const float*)d_in[4];
    const float* Whh  = (const float*)d_in[5];
    const float* bhh  = (const float*)d_in[6];
    const float* lw   = (const float*)d_in[7];
    const float* lb   = (const float*)d_in[8];
    const float* gotk = (const float*)d_in[9];
    float* out = (float*)d_out;

    float* out_probs = out;                        // [B,S,O]
    float* out_pre   = out + (size_t)16777216;     // [B,S,H]
    float* out_samp  = out + (size_t)50331648;     // [B,S,O]
    float* out_hx    = out + (size_t)67108864;     // [B,H]

    k_idx<<<RWS/8, 256>>>(gt, gotk);
    k_yT <<<65536, 256>>>(y);
    k_h0 <<<Bb*Hh/256, 256>>>(hx);
    k_gi <<<dim3(G3/TN, RWS/TM), 256>>>(Wih, bih);

    for (int s = 0; s < Ss; ++s){
        k_gh   <<<dim3(G3/TN, Bb/TM, 4), 256>>>(Whh, s);
        k_gates<<<Bb*Hh/256, 256>>>(bhh, out_pre, s);
    }

    k_logits <<<dim3(Oo/TN, RWS/TM), 256>>>(lw, lb, out_probs);
    k_softmax<<<RWS, 128>>>(out_probs, out_samp);
    k_hxout  <<<Bb*Hh/256, 256>>>(out_hx);
}

// round 2
// speedup vs baseline: 1.0158x; 1.0158x over previous
#include <cuda_runtime.h>
#include <math.h>

#define Bb 128
#define Ss 256
#define Ii 512
#define Oo 512
#define Hh 1024
#define IO 1024      // I + O
#define G3 3072      // 3*H
#define RWS (Ss*Bb)  // 32768 rows

#define TM 64
#define TN 64
#define KT 16
#define SSTR 68      // padded smem row stride (floats)

// ---------------- scratch (static __device__, allocation-free) ----------------
__device__ float g_yT[16777216];    // [s*B+b][I]   permuted y
__device__ int   g_idx[RWS];        // one-hot target index per row
__device__ float g_gi[100663296];   // [s*B+b][3H]  input-side gate preacts
__device__ float g_gh4[4*Bb*G3];    // 4 K-split partials of h @ Whh^T
__device__ float g_hs[33685504];    // [(s+1)][B][H], slot 0 = hx
__device__ float g_hsB[33554432];   // [b*S+s][H]   hs in output layout for logits GEMM

// ---------------- packed-f32x2 helpers ----------------
__device__ __forceinline__ unsigned long long pack2(float x){
    unsigned long long r;
    asm("mov.b64 %0, {%1, %1};" : "=l"(r) : "f"(x));
    return r;
}
__device__ __forceinline__ float2 unpk(unsigned long long v){
    float2 r;
    asm("mov.b64 {%0, %1}, %2;" : "=f"(r.x), "=f"(r.y) : "l"(v));
    return r;
}
#define FF(d,a,b) asm("fma.rn.f32x2 %0, %1, %2, %0;" : "+l"(d) : "l"(a), "l"(b))

// ---------------- shared GEMM core: C[64x64] tile of A[M,K] @ W[N,K]^T ----------------
// 256 threads, 4x4 micro-tile per thread, f32x2 packed FMA (2 fp32 FMA / instr).
__device__ __forceinline__ void gemm_core(
    const float* __restrict__ A, int lda,
    const float* __restrict__ W, int ldw,
    int rowBase, int colBase, int k0, int nk,
    unsigned long long acc[4][2])
{
    __shared__ __align__(16) float shA[KT*SSTR];
    __shared__ __align__(16) float shB[KT*SSTR];
    const int tid = threadIdx.x;
    const int tx = tid & 15, ty = tid >> 4;
    const int lk = tid & 15, lm = tid >> 4;

    for (int kc = 0; kc < nk; ++kc) {
        const int kb = k0 + kc*KT + lk;
        #pragma unroll
        for (int i = 0; i < 4; ++i) {
            shA[lk*SSTR + lm + i*16] = A[(size_t)(rowBase + lm + i*16)*lda + kb];
            shB[lk*SSTR + lm + i*16] = W[(size_t)(colBase + lm + i*16)*ldw + kb];
        }
        __syncthreads();
        #pragma unroll
        for (int kk = 0; kk < KT; ++kk) {
            float4 av = *reinterpret_cast<const float4*>(shA + kk*SSTR + (ty<<2));
            ulonglong2 bv = *reinterpret_cast<const ulonglong2*>(shB + kk*SSTR + (tx<<2));
            unsigned long long a0=pack2(av.x), a1=pack2(av.y), a2=pack2(av.z), a3=pack2(av.w);
            FF(acc[0][0],a0,bv.x); FF(acc[0][1],a0,bv.y);
            FF(acc[1][0],a1,bv.x); FF(acc[1][1],a1,bv.y);
            FF(acc[2][0],a2,bv.x); FF(acc[2][1],a2,bv.y);
            FF(acc[3][0],a3,bv.x); FF(acc[3][1],a3,bv.y);
        }
        __syncthreads();
    }
}

// ---------------- prep kernels ----------------
// One warp per row r = s*B+b: find index of the one-hot teacher-forcing target.
__global__ void k_idx(const float* __restrict__ gt, const float* __restrict__ gotoken){
    int w = (blockIdx.x*blockDim.x + threadIdx.x) >> 5;
    int lane = threadIdx.x & 31;
    if (w >= RWS) return;
    int s = w / Bb, b = w % Bb;
    const float* src = (s == 0) ? gotoken : gt + ((size_t)b*Ss + (s-1))*Oo;
    int found = Oo - 1;
    for (int o = lane; o < Oo; o += 32)
        if (src[o] > 0.5f) found = o;
    #pragma unroll
    for (int off = 16; off; off >>= 1)
        found = min(found, __shfl_xor_sync(0xffffffffu, found, off));
    if (lane == 0) g_idx[w] = found;
}

// Permute y[b][s][i] -> yT[s*B+b][i]
__global__ void k_yT(const float* __restrict__ y){
    size_t t = (size_t)blockIdx.x*blockDim.x + threadIdx.x;
    if (t >= (size_t)RWS*Ii) return;
    int i = (int)(t % Ii); int r = (int)(t / Ii);
    int s = r / Bb, b = r % Bb;
    g_yT[t] = y[((size_t)b*Ss + s)*Ii + i];
}

__global__ void k_h0(const float* __restrict__ hx){
    int t = blockIdx.x*blockDim.x + threadIdx.x;
    if (t < Bb*Hh) g_hs[t] = hx[t];
}

// ---------------- gi GEMM: gi[r][g] = yT[r]·Wih[g,:I] + bih[g] + Wih[g, I+idx[r]] ----------------
__global__ void k_gi(const float* __restrict__ Wih, const float* __restrict__ bih){
    unsigned long long acc[4][2] = {};
    int rowBase = blockIdx.y*TM, colBase = blockIdx.x*TN;
    gemm_core(g_yT, Ii, Wih, IO, rowBase, colBase, 0, Ii/KT, acc);
    int tx = threadIdx.x & 15, ty = threadIdx.x >> 4;
    #pragma unroll
    for (int i = 0; i < 4; ++i){
        int row = rowBase + (ty<<2) + i;
        int idx = g_idx[row];
        #pragma unroll
        for (int j = 0; j < 2; ++j){
            float2 v = unpk(acc[i][j]);
            int n = colBase + (tx<<2) + (j<<1);
            g_gi[(size_t)row*G3 + n]     = v.x + bih[n]   + Wih[(size_t)n*IO + Ii + idx];
            g_gi[(size_t)row*G3 + n + 1] = v.y + bih[n+1] + Wih[(size_t)(n+1)*IO + Ii + idx];
        }
    }
}

// ---------------- per-step GEMM: gh partial = h_prev @ Whh^T, K split 4 ways ----------------
__global__ void k_gh(const float* __restrict__ Whh, int s){
    unsigned long long acc[4][2] = {};
    int rowBase = blockIdx.y*TM, colBase = blockIdx.x*TN;
    int kz = blockIdx.z;
    const float* hprev = g_hs + (size_t)s*Bb*Hh;
    gemm_core(hprev, Hh, Whh, Hh, rowBase, colBase, kz*(Hh/4), (Hh/4)/KT, acc);
    int tx = threadIdx.x & 15, ty = threadIdx.x >> 4;
    float* dst = g_gh4 + (size_t)kz*Bb*G3;
    #pragma unroll
    for (int i = 0; i < 4; ++i){
        int row = rowBase + (ty<<2) + i;
        #pragma unroll
        for (int j = 0; j < 2; ++j){
            float2 v = unpk(acc[i][j]);
            int n = colBase + (tx<<2) + (j<<1);
            dst[(size_t)row*G3 + n]   = v.x;
            dst[(size_t)row*G3 + n+1] = v.y;
        }
    }
}

// ---------------- per-step gates (sums the 4 K-split partials, fixed order) ----------------
__global__ void k_gates(const float* __restrict__ bhh, float* __restrict__ pre_out, int s){
    int t = blockIdx.x*blockDim.x + threadIdx.x;
    if (t >= Bb*Hh) return;
    int b = t >> 10, j = t & 1023;
    size_t gio = ((size_t)s*Bb + b)*G3 + j;
    float i_r = g_gi[gio], i_z = g_gi[gio + Hh], i_n = g_gi[gio + 2*Hh];
    size_t gho = (size_t)b*G3 + j;
    float h_r = bhh[j], h_z = bhh[Hh + j], h_n = bhh[2*Hh + j];
    #pragma unroll
    for (int kz = 0; kz < 4; ++kz){
        size_t o = (size_t)kz*Bb*G3 + gho;
        h_r += g_gh4[o]; h_z += g_gh4[o + Hh]; h_n += g_gh4[o + 2*Hh];
    }
    float rg = 1.f/(1.f + expf(-(i_r + h_r)));
    float zg = 1.f/(1.f + expf(-(i_z + h_z)));
    float pre = i_n + rg*h_n;
    float ng = tanhf(pre);
    float hp = g_hs[((size_t)s*Bb + b)*Hh + j];
    float hy = ng + zg*(hp - ng);
    g_hs [((size_t)(s+1)*Bb + b)*Hh + j] = hy;
    g_hsB[((size_t)b*Ss + s)*Hh + j]     = hy;
    pre_out[((size_t)b*Ss + s)*Hh + j]   = pre;
}

// ---------------- logits GEMM: logits[b*S+s][o] = hsB·lin_w[o]^T + lin_b[o] ----------------
__global__ void k_logits(const float* __restrict__ lw, const float* __restrict__ lb,
                         float* __restrict__ outp){
    unsigned long long acc[4][2] = {};
    int rowBase = blockIdx.y*TM, colBase = blockIdx.x*TN;
    gemm_core(g_hsB, Hh, lw, Hh, rowBase, colBase, 0, Hh/KT, acc);
    int tx = threadIdx.x & 15, ty = threadIdx.x >> 4;
    #pragma unroll
    for (int i = 0; i < 4; ++i){
        int row = rowBase + (ty<<2) + i;
        #pragma unroll
        for (int j = 0; j < 2; ++j){
            float2 v = unpk(acc[i][j]);
            int n = colBase + (tx<<2) + (j<<1);
            outp[(size_t)row*Oo + n]   = v.x + lb[n];
            outp[(size_t)row*Oo + n+1] = v.y + lb[n+1];
        }
    }
}

// ---------------- softmax + argmax(one-hot), in place over logits ----------------
__global__ void k_softmax(float* __restrict__ probs, float* __restrict__ samp){
    __shared__ float sv[128];
    __shared__ int   si[128];
    int row = blockIdx.x;
    int t = threadIdx.x;
    float* lg = probs + (size_t)row*Oo;
    float v[4];
    #pragma unroll
    for (int i = 0; i < 4; ++i) v[i] = lg[t + i*128];
    float lmax = v[0]; int lidx = t;
    #pragma unroll
    for (int i = 1; i < 4; ++i)
        if (v[i] > lmax){ lmax = v[i]; lidx = t + i*128; }
    sv[t] = lmax; si[t] = lidx; __syncthreads();
    for (int off = 64; off; off >>= 1){
        if (t < off){
            float v2 = sv[t+off]; int i2 = si[t+off];
            if (v2 > sv[t] || (v2 == sv[t] && i2 < si[t])){ sv[t] = v2; si[t] = i2; }
        }
        __syncthreads();
    }
    float rmax = sv[0]; int ridx = si[0];
    __syncthreads();
    float e[4]; float ls = 0.f;
    #pragma unroll
    for (int i = 0; i < 4; ++i){ e[i] = expf(v[i] - rmax); ls += e[i]; }
    sv[t] = ls; __syncthreads();
    for (int off = 64; off; off >>= 1){
        if (t < off) sv[t] += sv[t+off];
        __syncthreads();
    }
    float inv = 1.f/sv[0];
    float* sp = samp + (size_t)row*Oo;
    #pragma unroll
    for (int i = 0; i < 4; ++i){
        int p = t + i*128;
        lg[p] = e[i]*inv;
        sp[p] = (p == ridx) ? 1.f : 0.f;
    }
}

__global__ void k_hxout(float* __restrict__ out){
    int t = blockIdx.x*blockDim.x + threadIdx.x;
    if (t < Bb*Hh) out[t] = g_hs[(size_t)Ss*Bb*Hh + t];
}

// ---------------- launch ----------------
extern "C" void kernel_launch(void* const* d_in, const int* in_sizes, int n_in,
                              void* d_out, int out_size){
    const float* y    = (const float*)d_in[0];
    const float* gt   = (const float*)d_in[1];
    const float* hx   = (const float*)d_in[2];
    const float* Wih  = (const float*)d_in[3];
    const float* bih  = (const float*)d_in[4];
    const float* Whh  = (const float*)d_in[5];
    const float* bhh  = (const float*)d_in[6];
    const float* lw   = (const float*)d_in[7];
    const float* lb   = (const float*)d_in[8];
    const float* gotk = (const float*)d_in[9];
    float* out = (float*)d_out;

    float* out_probs = out;                        // [B,S,O]
    float* out_pre   = out + (size_t)16777216;     // [B,S,H]
    float* out_samp  = out + (size_t)50331648;     // [B,S,O]
    float* out_hx    = out + (size_t)67108864;     // [B,H]

    k_idx<<<RWS/8, 256>>>(gt, gotk);
    k_yT <<<65536, 256>>>(y);
    k_h0 <<<Bb*Hh/256, 256>>>(hx);
    k_gi <<<dim3(G3/TN, RWS/TM), 256>>>(Wih, bih);

    for (int s = 0; s < Ss; ++s){
        k_gh   <<<dim3(G3/TN, Bb/TM, 4), 256>>>(Whh, s);
        k_gates<<<Bb*Hh/256, 256>>>(bhh, out_pre, s);
    }

    k_logits <<<dim3(Oo/TN, RWS/TM), 256>>>(lw, lb, out_probs);
    k_softmax<<<RWS, 128>>>(out_probs, out_samp);
    k_hxout  <<<Bb*Hh/256, 256>>>(out_hx);
}

// round 7
// speedup vs baseline: 1.2814x; 1.2614x over previous
#include <cuda_runtime.h>
#include <cuda_bf16.h>
#include <mma.h>
#include <math.h>
#include <cstdint>

using namespace nvcuda;

#define Bb 128
#define Ss 256
#define Ii 512
#define Oo 512
#define Hh 1024
#define IO 1024
#define G3 3072
#define RWS (Ss*Bb)

#define TM 64
#define TN 64
#define KT 16
#define SSTR 68

// ---------------- scratch ----------------
__device__ __align__(16) float g_yT[16777216];    // [s*B+b][I]
__device__ int   g_idx[RWS];
__device__ __align__(16) float g_gi[100663296];   // [s*B+b][3H] (incl bias+gather)
__device__ __align__(16) float g_gh4[4*Bb*G3];    // 4 K-split partials
__device__ __align__(16) float g_hs[33685504];    // [(s+1)][B][H]
__device__ __align__(16) float g_hsB[33554432];   // [b*S+s][H]
__device__ __align__(16) __nv_bfloat16 g_WhhHi[G3*1024], g_WhhLo[G3*1024];

// ---------------- packed-f32x2 helpers (R1 scalar GEMM) ----------------
__device__ __forceinline__ unsigned long long pack2(float x){
    unsigned long long r;
    asm("mov.b64 %0, {%1, %1};" : "=l"(r) : "f"(x));
    return r;
}
__device__ __forceinline__ float2 unpk(unsigned long long v){
    float2 r;
    asm("mov.b64 {%0, %1}, %2;" : "=f"(r.x), "=f"(r.y) : "l"(v));
    return r;
}
#define FF(d,a,b) asm("fma.rn.f32x2 %0, %1, %2, %0;" : "+l"(d) : "l"(a), "l"(b))

__device__ __forceinline__ void gemm_core(
    const float* __restrict__ A, int lda,
    const float* __restrict__ W, int ldw,
    int rowBase, int colBase, int k0, int nk,
    unsigned long long acc[4][2])
{
    __shared__ __align__(16) float shA[KT*SSTR];
    __shared__ __align__(16) float shB[KT*SSTR];
    const int tid = threadIdx.x;
    const int tx = tid & 15, ty = tid >> 4;
    const int lk = tid & 15, lm = tid >> 4;
    for (int kc = 0; kc < nk; ++kc) {
        const int kb = k0 + kc*KT + lk;
        #pragma unroll
        for (int i = 0; i < 4; ++i) {
            shA[lk*SSTR + lm + i*16] = A[(size_t)(rowBase + lm + i*16)*lda + kb];
            shB[lk*SSTR + lm + i*16] = W[(size_t)(colBase + lm + i*16)*ldw + kb];
        }
        __syncthreads();
        #pragma unroll
        for (int kk = 0; kk < KT; ++kk) {
            float4 av = *reinterpret_cast<const float4*>(shA + kk*SSTR + (ty<<2));
            ulonglong2 bv = *reinterpret_cast<const ulonglong2*>(shB + kk*SSTR + (tx<<2));
            unsigned long long a0=pack2(av.x), a1=pack2(av.y), a2=pack2(av.z), a3=pack2(av.w);
            FF(acc[0][0],a0,bv.x); FF(acc[0][1],a0,bv.y);
            FF(acc[1][0],a1,bv.x); FF(acc[1][1],a1,bv.y);
            FF(acc[2][0],a2,bv.x); FF(acc[2][1],a2,bv.y);
            FF(acc[3][0],a3,bv.x); FF(acc[3][1],a3,bv.y);
        }
        __syncthreads();
    }
}

// ---------------- prep kernels (R1 verbatim) ----------------
__global__ void k_idx(const float* __restrict__ gt, const float* __restrict__ gotoken){
    int w = (blockIdx.x*blockDim.x + threadIdx.x) >> 5;
    int lane = threadIdx.x & 31;
    if (w >= RWS) return;
    int s = w / Bb, b = w % Bb;
    const float* src = (s == 0) ? gotoken : gt + ((size_t)b*Ss + (s-1))*Oo;
    int found = Oo - 1;
    for (int o = lane; o < Oo; o += 32)
        if (src[o] > 0.5f) found = o;
    #pragma unroll
    for (int off = 16; off; off >>= 1)
        found = min(found, __shfl_xor_sync(0xffffffffu, found, off));
    if (lane == 0) g_idx[w] = found;
}

__global__ void k_yT(const float* __restrict__ y){
    size_t t = (size_t)blockIdx.x*blockDim.x + threadIdx.x;
    if (t >= (size_t)RWS*Ii) return;
    int i = (int)(t % Ii); int r = (int)(t / Ii);
    int s = r / Bb, b = r % Bb;
    g_yT[t] = y[((size_t)b*Ss + s)*Ii + i];
}

__global__ void k_h0(const float* __restrict__ hx){
    int t = blockIdx.x*blockDim.x + threadIdx.x;
    if (t < Bb*Hh) g_hs[t] = hx[t];
}

// NEW: elementwise hi/lo split of Whh (index-trivial)
__global__ void k_convWhh(const float* __restrict__ Whh){
    int t = blockIdx.x*blockDim.x + threadIdx.x;   // total 3145728
    float v = Whh[t];
    __nv_bfloat16 h = __float2bfloat16(v);
    g_WhhHi[t] = h;
    g_WhhLo[t] = __float2bfloat16(v - __bfloat162float(h));
}

// ---------------- gi GEMM (R1 scalar, verbatim) ----------------
__global__ void k_gi(const float* __restrict__ Wih, const float* __restrict__ bih){
    unsigned long long acc[4][2] = {};
    int rowBase = blockIdx.y*TM, colBase = blockIdx.x*TN;
    gemm_core(g_yT, Ii, Wih, IO, rowBase, colBase, 0, Ii/KT, acc);
    int tx = threadIdx.x & 15, ty = threadIdx.x >> 4;
    #pragma unroll
    for (int i = 0; i < 4; ++i){
        int row = rowBase + (ty<<2) + i;
        int idx = g_idx[row];
        #pragma unroll
        for (int j = 0; j < 2; ++j){
            float2 v = unpk(acc[i][j]);
            int n = colBase + (tx<<2) + (j<<1);
            g_gi[(size_t)row*G3 + n]     = v.x + bih[n]   + Wih[(size_t)n*IO + Ii + idx];
            g_gi[(size_t)row*G3 + n + 1] = v.y + bih[n+1] + Wih[(size_t)(n+1)*IO + Ii + idx];
        }
    }
}

// ---------------- NEW: wmma recurrence GEMM ----------------
typedef wmma::fragment<wmma::matrix_a, 16,16,16, __nv_bfloat16, wmma::row_major> FragA;
typedef wmma::fragment<wmma::matrix_b, 16,16,16, __nv_bfloat16, wmma::col_major> FragB;
typedef wmma::fragment<wmma::accumulator, 16,16,16, float> FragC;

#define SROW 20
#define SROW_E 40

__global__ void __launch_bounds__(256, 1) k_ghW(int s){
    __shared__ __align__(16) uint32_t sAHi[128*SROW], sALo[128*SROW];
    __shared__ __align__(16) uint32_t sBHi[128*SROW], sBLo[128*SROW];
    int nb = blockIdx.x, kz = blockIdx.y;
    int t = threadIdx.x;
    const float* Asrc = g_hs + (size_t)s*Bb*Hh;    // [128][1024] fp32
    int k0 = kz*256, nBase = nb*128;

    FragC acc[2][4];
    #pragma unroll
    for (int mi = 0; mi < 2; ++mi)
        #pragma unroll
        for (int ni = 0; ni < 4; ++ni) wmma::fill_fragment(acc[mi][ni], 0.f);

    int w = t >> 5;
    int rowOff = (w&3)*32, colOff = (w>>2)*64;
    const __nv_bfloat16* eAh = reinterpret_cast<const __nv_bfloat16*>(sAHi);
    const __nv_bfloat16* eAl = reinterpret_cast<const __nv_bfloat16*>(sALo);
    const __nv_bfloat16* eBh = reinterpret_cast<const __nv_bfloat16*>(sBHi);
    const __nv_bfloat16* eBl = reinterpret_cast<const __nv_bfloat16*>(sBLo);

    for (int c = 0; c < 8; ++c){
        int kc = k0 + c*32;
        // A: fp32 -> hi/lo bf16 in-kernel (512 tasks of 8 elements)
        #pragma unroll
        for (int it = 0; it < 2; ++it){
            int idx = it*256 + t;
            int row = idx >> 2, seg = idx & 3;
            const float* p = Asrc + (size_t)row*1024 + kc + seg*8;
            float4 v0 = *reinterpret_cast<const float4*>(p);
            float4 v1 = *reinterpret_cast<const float4*>(p + 4);
            uint4 hi, lo;
            {
                __nv_bfloat16 h0=__float2bfloat16(v0.x), h1=__float2bfloat16(v0.y);
                __nv_bfloat16 l0=__float2bfloat16(v0.x-__bfloat162float(h0));
                __nv_bfloat16 l1=__float2bfloat16(v0.y-__bfloat162float(h1));
                hi.x = ((uint32_t)__bfloat16_as_ushort(h1)<<16) | __bfloat16_as_ushort(h0);
                lo.x = ((uint32_t)__bfloat16_as_ushort(l1)<<16) | __bfloat16_as_ushort(l0);
                h0=__float2bfloat16(v0.z); h1=__float2bfloat16(v0.w);
                l0=__float2bfloat16(v0.z-__bfloat162float(h0));
                l1=__float2bfloat16(v0.w-__bfloat162float(h1));
                hi.y = ((uint32_t)__bfloat16_as_ushort(h1)<<16) | __bfloat16_as_ushort(h0);
                lo.y = ((uint32_t)__bfloat16_as_ushort(l1)<<16) | __bfloat16_as_ushort(l0);
                h0=__float2bfloat16(v1.x); h1=__float2bfloat16(v1.y);
                l0=__float2bfloat16(v1.x-__bfloat162float(h0));
                l1=__float2bfloat16(v1.y-__bfloat162float(h1));
                hi.z = ((uint32_t)__bfloat16_as_ushort(h1)<<16) | __bfloat16_as_ushort(h0);
                lo.z = ((uint32_t)__bfloat16_as_ushort(l1)<<16) | __bfloat16_as_ushort(l0);
                h0=__float2bfloat16(v1.z); h1=__float2bfloat16(v1.w);
                l0=__float2bfloat16(v1.z-__bfloat162float(h0));
                l1=__float2bfloat16(v1.w-__bfloat162float(h1));
                hi.w = ((uint32_t)__bfloat16_as_ushort(h1)<<16) | __bfloat16_as_ushort(h0);
                lo.w = ((uint32_t)__bfloat16_as_ushort(l1)<<16) | __bfloat16_as_ushort(l0);
            }
            *reinterpret_cast<uint4*>(sAHi + row*SROW + seg*4) = hi;
            *reinterpret_cast<uint4*>(sALo + row*SROW + seg*4) = lo;
        }
        // B: bf16 hi/lo copies from pre-split Whh
        #pragma unroll
        for (int it = 0; it < 2; ++it){
            int idx = it*256 + t;
            int row = idx >> 2, seg = idx & 3;
            size_t off = (size_t)(nBase + row)*1024 + kc + seg*8;
            *reinterpret_cast<uint4*>(sBHi + row*SROW + seg*4) =
                *reinterpret_cast<const uint4*>(g_WhhHi + off);
            *reinterpret_cast<uint4*>(sBLo + row*SROW + seg*4) =
                *reinterpret_cast<const uint4*>(g_WhhLo + off);
        }
        __syncthreads();
        #pragma unroll
        for (int ks = 0; ks < 2; ++ks){
            FragA ah[2], al[2];
            #pragma unroll
            for (int mi = 0; mi < 2; ++mi){
                wmma::load_matrix_sync(ah[mi], eAh + (rowOff + mi*16)*SROW_E + ks*16, SROW_E);
                wmma::load_matrix_sync(al[mi], eAl + (rowOff + mi*16)*SROW_E + ks*16, SROW_E);
            }
            #pragma unroll
            for (int ni = 0; ni < 4; ++ni){
                FragB bh, bl;
                wmma::load_matrix_sync(bh, eBh + (colOff + ni*16)*SROW_E + ks*16, SROW_E);
                wmma::load_matrix_sync(bl, eBl + (colOff + ni*16)*SROW_E + ks*16, SROW_E);
                #pragma unroll
                for (int mi = 0; mi < 2; ++mi){
                    wmma::mma_sync(acc[mi][ni], ah[mi], bh, acc[mi][ni]);
                    wmma::mma_sync(acc[mi][ni], ah[mi], bl, acc[mi][ni]);
                    wmma::mma_sync(acc[mi][ni], al[mi], bh, acc[mi][ni]);
                }
            }
        }
        __syncthreads();
    }
    float* dst = g_gh4 + (size_t)kz*Bb*G3;
    #pragma unroll
    for (int mi = 0; mi < 2; ++mi)
        #pragma unroll
        for (int ni = 0; ni < 4; ++ni)
            wmma::store_matrix_sync(dst + (size_t)(rowOff + mi*16)*G3
                                        + nBase + colOff + ni*16,
                                    acc[mi][ni], G3, wmma::mem_row_major);
}

// ---------------- gates (R1 verbatim) ----------------
__global__ void k_gates(const float* __restrict__ bhh, float* __restrict__ pre_out, int s){
    int t = blockIdx.x*blockDim.x + threadIdx.x;
    if (t >= Bb*Hh) return;
    int b = t >> 10, j = t & 1023;
    size_t gio = ((size_t)s*Bb + b)*G3 + j;
    float i_r = g_gi[gio], i_z = g_gi[gio + Hh], i_n = g_gi[gio + 2*Hh];
    size_t gho = (size_t)b*G3 + j;
    float h_r = bhh[j], h_z = bhh[Hh + j], h_n = bhh[2*Hh + j];
    #pragma unroll
    for (int kz = 0; kz < 4; ++kz){
        size_t o = (size_t)kz*Bb*G3 + gho;
        h_r += g_gh4[o]; h_z += g_gh4[o + Hh]; h_n += g_gh4[o + 2*Hh];
    }
    float rg = 1.f/(1.f + expf(-(i_r + h_r)));
    float zg = 1.f/(1.f + expf(-(i_z + h_z)));
    float pre = i_n + rg*h_n;
    float ng = tanhf(pre);
    float hp = g_hs[((size_t)s*Bb + b)*Hh + j];
    float hy = ng + zg*(hp - ng);
    g_hs [((size_t)(s+1)*Bb + b)*Hh + j] = hy;
    g_hsB[((size_t)b*Ss + s)*Hh + j]     = hy;
    pre_out[((size_t)b*Ss + s)*Hh + j]   = pre;
}

// ---------------- logits GEMM (R1 scalar, verbatim) ----------------
__global__ void k_logits(const float* __restrict__ lw, const float* __restrict__ lb,
                         float* __restrict__ outp){
    unsigned long long acc[4][2] = {};
    int rowBase = blockIdx.y*TM, colBase = blockIdx.x*TN;
    gemm_core(g_hsB, Hh, lw, Hh, rowBase, colBase, 0, Hh/KT, acc);
    int tx = threadIdx.x & 15, ty = threadIdx.x >> 4;
    #pragma unroll
    for (int i = 0; i < 4; ++i){
        int row = rowBase + (ty<<2) + i;
        #pragma unroll
        for (int j = 0; j < 2; ++j){
            float2 v = unpk(acc[i][j]);
            int n = colBase + (tx<<2) + (j<<1);
            outp[(size_t)row*Oo + n]   = v.x + lb[n];
            outp[(size_t)row*Oo + n+1] = v.y + lb[n+1];
        }
    }
}

// ---------------- softmax + argmax (R1 verbatim) ----------------
__global__ void k_softmax(float* __restrict__ probs, float* __restrict__ samp){
    __shared__ float sv[128];
    __shared__ int   si[128];
    int row = blockIdx.x;
    int t = threadIdx.x;
    float* lg = probs + (size_t)row*Oo;
    float v[4];
    #pragma unroll
    for (int i = 0; i < 4; ++i) v[i] = lg[t + i*128];
    float lmax = v[0]; int lidx = t;
    #pragma unroll
    for (int i = 1; i < 4; ++i)
        if (v[i] > lmax){ lmax = v[i]; lidx = t + i*128; }
    sv[t] = lmax; si[t] = lidx; __syncthreads();
    for (int off = 64; off; off >>= 1){
        if (t < off){
            float v2 = sv[t+off]; int i2 = si[t+off];
            if (v2 > sv[t] || (v2 == sv[t] && i2 < si[t])){ sv[t] = v2; si[t] = i2; }
        }
        __syncthreads();
    }
    float rmax = sv[0]; int ridx = si[0];
    __syncthreads();
    float e[4]; float ls = 0.f;
    #pragma unroll
    for (int i = 0; i < 4; ++i){ e[i] = expf(v[i] - rmax); ls += e[i]; }
    sv[t] = ls; __syncthreads();
    for (int off = 64; off; off >>= 1){
        if (t < off) sv[t] += sv[t+off];
        __syncthreads();
    }
    float inv = 1.f/sv[0];
    float* sp = samp + (size_t)row*Oo;
    #pragma unroll
    for (int i = 0; i < 4; ++i){
        int p = t + i*128;
        lg[p] = e[i]*inv;
        sp[p] = (p == ridx) ? 1.f : 0.f;
    }
}

__global__ void k_hxout(float* __restrict__ out){
    int t = blockIdx.x*blockDim.x + threadIdx.x;
    if (t < Bb*Hh) out[t] = g_hs[(size_t)Ss*Bb*Hh + t];
}

// ---------------- launch ----------------
extern "C" void kernel_launch(void* const* d_in, const int* in_sizes, int n_in,
                              void* d_out, int out_size){
    const float* y    = (const float*)d_in[0];
    const float* gt   = (const float*)d_in[1];
    const float* hx   = (const float*)d_in[2];
    const float* Wih  = (const float*)d_in[3];
    const float* bih  = (const float*)d_in[4];
    const float* Whh  = (const float*)d_in[5];
    const float* bhh  = (const float*)d_in[6];
    const float* lw   = (const float*)d_in[7];
    const float* lb   = (const float*)d_in[8];
    const float* gotk = (const float*)d_in[9];
    float* out = (float*)d_out;

    float* out_probs = out;
    float* out_pre   = out + (size_t)16777216;
    float* out_samp  = out + (size_t)50331648;
    float* out_hx    = out + (size_t)67108864;

    k_idx    <<<RWS/8, 256>>>(gt, gotk);
    k_yT     <<<65536, 256>>>(y);
    k_h0     <<<Bb*Hh/256, 256>>>(hx);
    k_convWhh<<<12288, 256>>>(Whh);
    k_gi     <<<dim3(G3/TN, RWS/TM), 256>>>(Wih, bih);

    for (int s = 0; s < Ss; ++s){
        k_ghW  <<<dim3(24, 4), 256>>>(s);
        k_gates<<<Bb*Hh/256, 256>>>(bhh, out_pre, s);
    }

    k_logits <<<dim3(Oo/TN, RWS/TM), 256>>>(lw, lb, out_probs);
    k_softmax<<<RWS, 128>>>(out_probs, out_samp);
    k_hxout  <<<Bb*Hh/256, 256>>>(out_hx);
}

// round 9
// speedup vs baseline: 1.5628x; 1.2196x over previous
#include <cuda_runtime.h>
#include <cuda_bf16.h>
#include <mma.h>
#include <math.h>
#include <cstdint>

using namespace nvcuda;

#define Bb 128
#define Ss 256
#define Ii 512
#define Oo 512
#define Hh 1024
#define IO 1024
#define G3 3072
#define RWS (Ss*Bb)

// ---------------- scratch ----------------
__device__ __align__(16) float g_yT[16777216];    // [s*B+b][I] fp32
__device__ int   g_idx[RWS];
__device__ __align__(16) float g_gi[100663296];   // [s*B+b][3H]
__device__ __align__(16) float g_gh4[4*Bb*G3];    // 4 K-split partials
__device__ __align__(16) float g_hs[33685504];    // [(s+1)][B][H]
__device__ __align__(16) float g_hsB[33554432];   // [b*S+s][H]
__device__ __align__(16) float g_lg[16777216];    // raw logits [b*S+s][512]
__device__ __align__(16) float g_WtgtT[Oo*G3];    // Wih[:,512+o] transposed [o][g]
__device__ __align__(16) __nv_bfloat16 g_WhhHi[G3*1024], g_WhhLo[G3*1024];
__device__ __align__(16) __nv_bfloat16 g_WihHi[G3*1024], g_WihLo[G3*1024];
__device__ __align__(16) __nv_bfloat16 g_LwHi[Oo*1024],  g_LwLo[Oo*1024];

// ---------------- wmma GEMM core (proven in R7) ----------------
typedef wmma::fragment<wmma::matrix_a, 16,16,16, __nv_bfloat16, wmma::row_major> FragA;
typedef wmma::fragment<wmma::matrix_b, 16,16,16, __nv_bfloat16, wmma::col_major> FragB;
typedef wmma::fragment<wmma::accumulator, 16,16,16, float> FragC;

#define SROW 20
#define SROW_E 40

// C[128x128] tile: dst[mBase+.., nBase+..] = A[mBase.., k0..] @ B[nBase.., k0..]^T
// A fp32 (converted in-kernel to hi/lo bf16), B pre-split bf16 hi/lo images.
__device__ __forceinline__ void wmma_gemm(
    const float* __restrict__ Asrc, int lda, int mBase,
    const __nv_bfloat16* __restrict__ BHi, const __nv_bfloat16* __restrict__ BLo,
    int ldb, int nBase, int k0, int nChunks,
    float* __restrict__ dst, int ldd)
{
    __shared__ __align__(16) uint32_t sAHi[128*SROW], sALo[128*SROW];
    __shared__ __align__(16) uint32_t sBHi[128*SROW], sBLo[128*SROW];
    int t = threadIdx.x;

    FragC acc[2][4];
    #pragma unroll
    for (int mi = 0; mi < 2; ++mi)
        #pragma unroll
        for (int ni = 0; ni < 4; ++ni) wmma::fill_fragment(acc[mi][ni], 0.f);

    int w = t >> 5;
    int rowOff = (w&3)*32, colOff = (w>>2)*64;
    const __nv_bfloat16* eAh = reinterpret_cast<const __nv_bfloat16*>(sAHi);
    const __nv_bfloat16* eAl = reinterpret_cast<const __nv_bfloat16*>(sALo);
    const __nv_bfloat16* eBh = reinterpret_cast<const __nv_bfloat16*>(sBHi);
    const __nv_bfloat16* eBl = reinterpret_cast<const __nv_bfloat16*>(sBLo);

    for (int c = 0; c < nChunks; ++c){
        int kc = k0 + c*32;
        // A: fp32 -> hi/lo bf16 into smem
        #pragma unroll
        for (int it = 0; it < 2; ++it){
            int idx = it*256 + t;
            int row = idx >> 2, seg = idx & 3;
            const float* p = Asrc + (size_t)(mBase + row)*lda + kc + seg*8;
            float4 v0 = *reinterpret_cast<const float4*>(p);
            float4 v1 = *reinterpret_cast<const float4*>(p + 4);
            uint4 hi, lo;
            {
                __nv_bfloat16 h0=__float2bfloat16(v0.x), h1=__float2bfloat16(v0.y);
                __nv_bfloat16 l0=__float2bfloat16(v0.x-__bfloat162float(h0));
                __nv_bfloat16 l1=__float2bfloat16(v0.y-__bfloat162float(h1));
                hi.x = ((uint32_t)__bfloat16_as_ushort(h1)<<16) | __bfloat16_as_ushort(h0);
                lo.x = ((uint32_t)__bfloat16_as_ushort(l1)<<16) | __bfloat16_as_ushort(l0);
                h0=__float2bfloat16(v0.z); h1=__float2bfloat16(v0.w);
                l0=__float2bfloat16(v0.z-__bfloat162float(h0));
                l1=__float2bfloat16(v0.w-__bfloat162float(h1));
                hi.y = ((uint32_t)__bfloat16_as_ushort(h1)<<16) | __bfloat16_as_ushort(h0);
                lo.y = ((uint32_t)__bfloat16_as_ushort(l1)<<16) | __bfloat16_as_ushort(l0);
                h0=__float2bfloat16(v1.x); h1=__float2bfloat16(v1.y);
                l0=__float2bfloat16(v1.x-__bfloat162float(h0));
                l1=__float2bfloat16(v1.y-__bfloat162float(h1));
                hi.z = ((uint32_t)__bfloat16_as_ushort(h1)<<16) | __bfloat16_as_ushort(h0);
                lo.z = ((uint32_t)__bfloat16_as_ushort(l1)<<16) | __bfloat16_as_ushort(l0);
                h0=__float2bfloat16(v1.z); h1=__float2bfloat16(v1.w);
                l0=__float2bfloat16(v1.z-__bfloat162float(h0));
                l1=__float2bfloat16(v1.w-__bfloat162float(h1));
                hi.w = ((uint32_t)__bfloat16_as_ushort(h1)<<16) | __bfloat16_as_ushort(h0);
                lo.w = ((uint32_t)__bfloat16_as_ushort(l1)<<16) | __bfloat16_as_ushort(l0);
            }
            *reinterpret_cast<uint4*>(sAHi + row*SROW + seg*4) = hi;
            *reinterpret_cast<uint4*>(sALo + row*SROW + seg*4) = lo;
        }
        // B: bf16 hi/lo copies from pre-split images
        #pragma unroll
        for (int it = 0; it < 2; ++it){
            int idx = it*256 + t;
            int row = idx >> 2, seg = idx & 3;
            size_t off = (size_t)(nBase + row)*ldb + kc + seg*8;
            *reinterpret_cast<uint4*>(sBHi + row*SROW + seg*4) =
                *reinterpret_cast<const uint4*>(BHi + off);
            *reinterpret_cast<uint4*>(sBLo + row*SROW + seg*4) =
                *reinterpret_cast<const uint4*>(BLo + off);
        }
        __syncthreads();
        #pragma unroll
        for (int ks = 0; ks < 2; ++ks){
            FragA ah[2], al[2];
            #pragma unroll
            for (int mi = 0; mi < 2; ++mi){
                wmma::load_matrix_sync(ah[mi], eAh + (rowOff + mi*16)*SROW_E + ks*16, SROW_E);
                wmma::load_matrix_sync(al[mi], eAl + (rowOff + mi*16)*SROW_E + ks*16, SROW_E);
            }
            #pragma unroll
            for (int ni = 0; ni < 4; ++ni){
                FragB bh, bl;
                wmma::load_matrix_sync(bh, eBh + (colOff + ni*16)*SROW_E + ks*16, SROW_E);
                wmma::load_matrix_sync(bl, eBl + (colOff + ni*16)*SROW_E + ks*16, SROW_E);
                #pragma unroll
                for (int mi = 0; mi < 2; ++mi){
                    wmma::mma_sync(acc[mi][ni], ah[mi], bh, acc[mi][ni]);
                    wmma::mma_sync(acc[mi][ni], ah[mi], bl, acc[mi][ni]);
                    wmma::mma_sync(acc[mi][ni], al[mi], bh, acc[mi][ni]);
                }
            }
        }
        __syncthreads();
    }
    #pragma unroll
    for (int mi = 0; mi < 2; ++mi)
        #pragma unroll
        for (int ni = 0; ni < 4; ++ni)
            wmma::store_matrix_sync(dst + (size_t)(mBase + rowOff + mi*16)*ldd
                                        + nBase + colOff + ni*16,
                                    acc[mi][ni], ldd, wmma::mem_row_major);
}

// ---------------- prep kernels ----------------
__global__ void k_idx(const float* __restrict__ gt, const float* __restrict__ gotoken){
    int w = (blockIdx.x*blockDim.x + threadIdx.x) >> 5;
    int lane = threadIdx.x & 31;
    if (w >= RWS) return;
    int s = w / Bb, b = w % Bb;
    const float* src = (s == 0) ? gotoken : gt + ((size_t)b*Ss + (s-1))*Oo;
    int found = Oo - 1;
    for (int o = lane; o < Oo; o += 32)
        if (src[o] > 0.5f) found = o;
    #pragma unroll
    for (int off = 16; off; off >>= 1)
        found = min(found, __shfl_xor_sync(0xffffffffu, found, off));
    if (lane == 0) g_idx[w] = found;
}

__global__ void k_yT(const float* __restrict__ y){
    size_t t = (size_t)blockIdx.x*blockDim.x + threadIdx.x;
    if (t >= (size_t)RWS*Ii) return;
    int i = (int)(t % Ii); int r = (int)(t / Ii);
    int s = r / Bb, b = r % Bb;
    g_yT[t] = y[((size_t)b*Ss + s)*Ii + i];
}

__global__ void k_h0(const float* __restrict__ hx){
    int t = blockIdx.x*blockDim.x + threadIdx.x;
    if (t < Bb*Hh) g_hs[t] = hx[t];
}

// elementwise hi/lo weight splits (index-trivial, proven pattern)
__global__ void k_convWhh(const float* __restrict__ W){
    int t = blockIdx.x*blockDim.x + threadIdx.x;   // 3145728
    float v = W[t];
    __nv_bfloat16 h = __float2bfloat16(v);
    g_WhhHi[t] = h;
    g_WhhLo[t] = __float2bfloat16(v - __bfloat162float(h));
}
__global__ void k_convWih(const float* __restrict__ W){
    int t = blockIdx.x*blockDim.x + threadIdx.x;   // 3145728
    float v = W[t];
    __nv_bfloat16 h = __float2bfloat16(v);
    g_WihHi[t] = h;
    g_WihLo[t] = __float2bfloat16(v - __bfloat162float(h));
}
__global__ void k_convLw(const float* __restrict__ W){
    int t = blockIdx.x*blockDim.x + threadIdx.x;   // 524288
    float v = W[t];
    __nv_bfloat16 h = __float2bfloat16(v);
    g_LwHi[t] = h;
    g_LwLo[t] = __float2bfloat16(v - __bfloat162float(h));
}

// transpose gather table: WtgtT[o][g] = Wih[g][512 + o]
__global__ void k_prepT(const float* __restrict__ Wih){
    __shared__ float tile[32][33];
    int gB = blockIdx.x*32, oB = blockIdx.y*32;
    int tx = threadIdx.x, ty = threadIdx.y;
    #pragma unroll
    for (int j = 0; j < 32; j += 8)
        tile[ty+j][tx] = Wih[(size_t)(gB + ty + j)*1024 + 512 + oB + tx];
    __syncthreads();
    #pragma unroll
    for (int j = 0; j < 32; j += 8)
        g_WtgtT[(size_t)(oB + ty + j)*3072 + gB + tx] = tile[tx][ty+j];
}

// ---------------- GEMM kernels ----------------
__global__ void __launch_bounds__(256, 1) k_giW(){
    wmma_gemm(g_yT, 512, blockIdx.y*128,
              g_WihHi, g_WihLo, 1024, blockIdx.x*128, 0, 16,
              g_gi, 3072);
}

__global__ void __launch_bounds__(256, 1) k_ghW(int s){
    wmma_gemm(g_hs + (size_t)s*Bb*Hh, 1024, 0,
              g_WhhHi, g_WhhLo, 1024, blockIdx.x*128, blockIdx.y*256, 8,
              g_gh4 + (size_t)blockIdx.y*Bb*G3, 3072);
}

__global__ void __launch_bounds__(256, 1) k_lwW(){
    wmma_gemm(g_hsB, 1024, blockIdx.y*128,
              g_LwHi, g_LwLo, 1024, blockIdx.x*128, 0, 32,
              g_lg, 512);
}

// gi epilogue: add bih + one-hot gather column (25165824 float4 tasks)
__global__ void k_giBias(const float* __restrict__ bih){
    int idx = blockIdx.x*blockDim.x + threadIdx.x;
    int row = idx / 768;
    int n4 = (idx - row*768)*4;
    int id = g_idx[row];
    float4 v = *reinterpret_cast<float4*>(g_gi + (size_t)row*3072 + n4);
    float4 b = *reinterpret_cast<const float4*>(bih + n4);
    float4 wv = *reinterpret_cast<const float4*>(g_WtgtT + (size_t)id*3072 + n4);
    v.x += b.x + wv.x; v.y += b.y + wv.y; v.z += b.z + wv.z; v.w += b.w + wv.w;
    *reinterpret_cast<float4*>(g_gi + (size_t)row*3072 + n4) = v;
}

// ---------------- gates (R7 verbatim) ----------------
__global__ void k_gates(const float* __restrict__ bhh, float* __restrict__ pre_out, int s){
    int t = blockIdx.x*blockDim.x + threadIdx.x;
    if (t >= Bb*Hh) return;
    int b = t >> 10, j = t & 1023;
    size_t gio = ((size_t)s*Bb + b)*G3 + j;
    float i_r = g_gi[gio], i_z = g_gi[gio + Hh], i_n = g_gi[gio + 2*Hh];
    size_t gho = (size_t)b*G3 + j;
    float h_r = bhh[j], h_z = bhh[Hh + j], h_n = bhh[2*Hh + j];
    #pragma unroll
    for (int kz = 0; kz < 4; ++kz){
        size_t o = (size_t)kz*Bb*G3 + gho;
        h_r += g_gh4[o]; h_z += g_gh4[o + Hh]; h_n += g_gh4[o + 2*Hh];
    }
    float rg = 1.f/(1.f + expf(-(i_r + h_r)));
    float zg = 1.f/(1.f + expf(-(i_z + h_z)));
    float pre = i_n + rg*h_n;
    float ng = tanhf(pre);
    float hp = g_hs[((size_t)s*Bb + b)*Hh + j];
    float hy = ng + zg*(hp - ng);
    g_hs [((size_t)(s+1)*Bb + b)*Hh + j] = hy;
    g_hsB[((size_t)b*Ss + s)*Hh + j]     = hy;
    pre_out[((size_t)b*Ss + s)*Hh + j]   = pre;
}

// ---------------- softmax + argmax (reads raw logits + lb) ----------------
__global__ void k_softmax(const float* __restrict__ lb,
                          float* __restrict__ probs, float* __restrict__ samp){
    __shared__ float sv[128];
    __shared__ int   si[128];
    int row = blockIdx.x;
    int t = threadIdx.x;
    const float* lgi = g_lg + (size_t)row*Oo;
    float v[4];
    #pragma unroll
    for (int i = 0; i < 4; ++i) v[i] = lgi[t + i*128] + lb[t + i*128];
    float lmax = v[0]; int lidx = t;
    #pragma unroll
    for (int i = 1; i < 4; ++i)
        if (v[i] > lmax){ lmax = v[i]; lidx = t + i*128; }
    sv[t] = lmax; si[t] = lidx; __syncthreads();
    for (int off = 64; off; off >>= 1){
        if (t < off){
            float v2 = sv[t+off]; int i2 = si[t+off];
            if (v2 > sv[t] || (v2 == sv[t] && i2 < si[t])){ sv[t] = v2; si[t] = i2; }
        }
        __syncthreads();
    }
    float rmax = sv[0]; int ridx = si[0];
    __syncthreads();
    float e[4]; float ls = 0.f;
    #pragma unroll
    for (int i = 0; i < 4; ++i){ e[i] = expf(v[i] - rmax); ls += e[i]; }
    sv[t] = ls; __syncthreads();
    for (int off = 64; off; off >>= 1){
        if (t < off) sv[t] += sv[t+off];
        __syncthreads();
    }
    float inv = 1.f/sv[0];
    float* lg = probs + (size_t)row*Oo;
    float* sp = samp + (size_t)row*Oo;
    #pragma unroll
    for (int i = 0; i < 4; ++i){
        int p = t + i*128;
        lg[p] = e[i]*inv;
        sp[p] = (p == ridx) ? 1.f : 0.f;
    }
}

__global__ void k_hxout(float* __restrict__ out){
    int t = blockIdx.x*blockDim.x + threadIdx.x;
    if (t < Bb*Hh) out[t] = g_hs[(size_t)Ss*Bb*Hh + t];
}

// ---------------- launch ----------------
extern "C" void kernel_launch(void* const* d_in, const int* in_sizes, int n_in,
                              void* d_out, int out_size){
    const float* y    = (const float*)d_in[0];
    const float* gt   = (const float*)d_in[1];
    const float* hx   = (const float*)d_in[2];
    const float* Wih  = (const float*)d_in[3];
    const float* bih  = (const float*)d_in[4];
    const float* Whh  = (const float*)d_in[5];
    const float* bhh  = (const float*)d_in[6];
    const float* lw   = (const float*)d_in[7];
    const float* lb   = (const float*)d_in[8];
    const float* gotk = (const float*)d_in[9];
    float* out = (float*)d_out;

    float* out_probs = out;
    float* out_pre   = out + (size_t)16777216;
    float* out_samp  = out + (size_t)50331648;
    float* out_hx    = out + (size_t)67108864;

    k_idx    <<<RWS/8, 256>>>(gt, gotk);
    k_yT     <<<65536, 256>>>(y);
    k_h0     <<<Bb*Hh/256, 256>>>(hx);
    k_convWhh<<<12288, 256>>>(Whh);
    k_convWih<<<12288, 256>>>(Wih);
    k_convLw <<<2048, 256>>>(lw);
    k_prepT  <<<dim3(96, 16), dim3(32, 8)>>>(Wih);

    k_giW    <<<dim3(24, 256), 256>>>();
    k_giBias <<<98304, 256>>>(bih);

    for (int s = 0; s < Ss; ++s){
        k_ghW  <<<dim3(24, 4), 256>>>(s);
        k_gates<<<Bb*Hh/256, 256>>>(bhh, out_pre, s);
    }

    k_lwW    <<<dim3(4, 256), 256>>>();
    k_softmax<<<RWS, 128>>>(lb, out_probs, out_samp);
    k_hxout  <<<Bb*Hh/256, 256>>>(out_hx);
}